// round 12
// baseline (speedup 1.0000x reference)
#include <cuda_runtime.h>
#include <cuda_fp16.h>
#include <cstdint>
#include <cstddef>

// 2-layer LSTM, T=1024, B=16, I=H=1024.
// SINGLE persistent kernel, both layers pipelined: interval s computes
// L0 step s and L1 step s-1 (1025 handoffs instead of 2048).
// L1's input A-frag == L0's h A-frag (same loads). L0 weights in smem,
// L1 weights in registers. R10-proven poll/release/staging machinery.
#define T_   1024
#define B_   16
#define H_   1024
#define NCTA 128
#define NTHR 256
#define WFRAG_L (NCTA*128*4*32*2)     // u32 per layer = 4,194,304
#define XFRAG_T 8192                  // u32 per timestep A-frag (32 KB)
#define HFRAG_SZ XFRAG_T
#define RED_STRIDE 544                // 16 rows * 34 floats per warp-row
// smem u32 map: s_x[2][8192] | s_wx0[16384] | s_wh0[16384] | s_red[16*544]f
#define SMEM_U32 (16384 + 16384 + 16384 + 16*RED_STRIDE)
#define SMEM_BYTES (SMEM_U32*4)       // 231424 <= 232448

__device__ __align__(16) uint32_t g_wfrag[2][WFRAG_L];
__device__ __align__(16) uint32_t g_xfrag0[(size_t)T_*XFRAG_T];
__device__ __align__(16) uint32_t g_h0f[2*HFRAG_SZ];
__device__ __align__(16) uint32_t g_h1f[2*HFRAG_SZ];
__device__ __align__(16) unsigned g_flags[NCTA];

// ---------------------------------------------------------------------------
__global__ void k_reset() {
    int i = blockIdx.x * blockDim.x + threadIdx.x;
    if (i < 2*HFRAG_SZ) { g_h0f[i] = 0u; g_h1f[i] = 0u; }
    if (i < NCTA) g_flags[i] = 0u;
}

// B-frag layout for [Wih;Whh]: idx = (((c*128+kk)*4+nt)*32+lane)*2+p
// lane=4g+tq ; W row = nt*H + c*8 + g ; k = (kk&63)*16 + 2tq + 8p + {0,1}
// kk<64 -> Wih, kk>=64 -> Whh
__global__ void k_conv_w(const float* __restrict__ Wih0, const float* __restrict__ Whh0,
                         const float* __restrict__ Wih1, const float* __restrict__ Whh1) {
    int layer = blockIdx.y;
    const float* Wih = layer ? Wih1 : Wih0;
    const float* Whh = layer ? Whh1 : Whh0;
    int stride = gridDim.x * blockDim.x;
    for (int idx = blockIdx.x * blockDim.x + threadIdx.x; idx < WFRAG_L; idx += stride) {
        int p    = idx & 1;
        int lane = (idx >> 1) & 31;
        int nt   = (idx >> 6) & 3;
        int kk   = (idx >> 8) & 127;
        int c    = idx >> 15;
        int g = lane >> 2, tq = lane & 3;
        int row = nt * H_ + c * 8 + g;
        int kl  = (kk & 63) * 16 + tq * 2 + p * 8;
        const float2 v = *reinterpret_cast<const float2*>(
            (kk < 64 ? Wih : Whh) + (size_t)row * H_ + kl);
        __half2 hv = __floats2half2_rn(v.x, v.y);
        g_wfrag[layer][idx] = *reinterpret_cast<uint32_t*>(&hv);
    }
}

// A-frag layout for x: per-t idx = (kk*32+lane)*4 + r ; b = g + 8*(r&1) ;
// k = kk*16 + 2tq + 8*(r>>1) + {0,1}
__global__ void k_conv_x(const float* __restrict__ x) {
    size_t total = (size_t)T_ * XFRAG_T;
    size_t stride = (size_t)gridDim.x * blockDim.x;
    for (size_t idx = (size_t)blockIdx.x * blockDim.x + threadIdx.x; idx < total; idx += stride) {
        int it = (int)(idx >> 13);
        int r8 = (int)(idx & (XFRAG_T - 1));
        int kk   = r8 >> 7;
        int lane = (r8 >> 2) & 31;
        int r    = r8 & 3;
        int g = lane >> 2, tq = lane & 3;
        int b  = g + ((r & 1) << 3);
        int kb = kk * 16 + tq * 2 + ((r >> 1) << 3);
        const float2 v = *reinterpret_cast<const float2*>(
            x + ((size_t)it * B_ + b) * H_ + kb);
        __half2 hv = __floats2half2_rn(v.x, v.y);
        g_xfrag0[idx] = *reinterpret_cast<uint32_t*>(&hv);
    }
}

// ---------------------------------------------------------------------------
__device__ __forceinline__ float tanh_ap(float v) {
    float r;
    asm("tanh.approx.f32 %0, %1;" : "=f"(r) : "f"(v));
    return r;
}
__device__ __forceinline__ float sigmoid_ap(float v) {
    return fmaf(tanh_ap(0.5f * v), 0.5f, 0.5f);
}

__device__ __forceinline__ void cpa16(uint32_t dst, const void* src) {
    asm volatile("cp.async.cg.shared.global [%0], [%1], 16;" :: "r"(dst), "l"(src));
}
#define CP_COMMIT asm volatile("cp.async.commit_group;")
#define CP_WAIT0  asm volatile("cp.async.wait_group 0;")

__device__ __forceinline__ uint4 ldcg4(const uint4* p) {
    uint4 v;
    asm volatile("ld.global.cg.v4.u32 {%0,%1,%2,%3}, [%4];"
                 : "=r"(v.x), "=r"(v.y), "=r"(v.z), "=r"(v.w) : "l"(p));
    return v;
}
__device__ __forceinline__ unsigned ld_acq(const unsigned* p) {
    unsigned v;
    asm volatile("ld.acquire.gpu.global.u32 %0, [%1];" : "=r"(v) : "l"(p));
    return v;
}
__device__ __forceinline__ void st_release_u32(unsigned* p, unsigned v) {
    asm volatile("st.release.gpu.global.u32 [%0], %1;" :: "l"(p), "r"(v) : "memory");
}

__device__ __forceinline__ void mma16816(float* acc, const uint4& a, const uint2& b) {
    asm volatile(
        "mma.sync.aligned.m16n8k16.row.col.f32.f16.f16.f32 "
        "{%0,%1,%2,%3}, {%4,%5,%6,%7}, {%8,%9}, {%0,%1,%2,%3};\n"
        : "+f"(acc[0]), "+f"(acc[1]), "+f"(acc[2]), "+f"(acc[3])
        : "r"(a.x), "r"(a.y), "r"(a.z), "r"(a.w), "r"(b.x), "r"(b.y));
}

__global__ void __launch_bounds__(NTHR, 1)
k_lstm(const float* __restrict__ bih0, const float* __restrict__ bhh0,
       const float* __restrict__ bih1, const float* __restrict__ bhh1,
       float* __restrict__ out, float* __restrict__ nh, float* __restrict__ nc) {
    extern __shared__ uint32_t smem[];
    uint32_t* s_x0  = smem;                     // x parity 0
    uint32_t* s_x1  = smem + 8192;              // x parity 1
    uint32_t* s_wx0 = smem + 16384;             // L0 Wih frags (kk 0..63)
    uint32_t* s_wh0 = smem + 32768;             // L0 Whh frags (kk 64..127)
    float*    s_red = (float*)(smem + 49152);   // 16 rows * 544

    uint32_t sbase;
    asm("{ .reg .u64 t; cvta.to.shared.u64 t, %1; cvt.u32.u64 %0, t; }"
        : "=r"(sbase) : "l"(smem));

    const int tid = threadIdx.x, warp = tid >> 5, lane = tid & 31;
    const int cblk = blockIdx.x;
    const int g = lane >> 2, tq = lane & 3;

    // ---- L1 weights -> registers: warp covers in-kk [8w,8w+8), h1-kk 64+[8w,8w+8)
    uint2 bi1r[8][4], bh1r[8][4];
    {
        const uint32_t* wf1 = g_wfrag[1] + (size_t)cblk * 32768;
        #pragma unroll
        for (int j = 0; j < 8; j++) {
            #pragma unroll
            for (int nt = 0; nt < 4; nt++) {
                int kki = warp * 8 + j;
                int kkh = 64 + warp * 8 + j;
                bi1r[j][nt] = *(const uint2*)&wf1[((kki * 4 + nt) * 32 + lane) * 2];
                bh1r[j][nt] = *(const uint2*)&wf1[((kkh * 4 + nt) * 32 + lane) * 2];
            }
        }
    }

    // ---- prologue: L0 weights (128 KB) + x[0] into smem via cp.async ----
    {
        const uint4* w0 = (const uint4*)(g_wfrag[0] + (size_t)cblk * 32768);
        const uint32_t A_WX = sbase + 16384u*4u;
        #pragma unroll
        for (int i = 0; i < 32; i++)
            cpa16(A_WX + (tid + i*NTHR)*16u, w0 + tid + i*NTHR);
        const uint4* xs = (const uint4*)g_xfrag0;
        #pragma unroll
        for (int i = 0; i < 8; i++)
            cpa16(sbase + (tid + i*NTHR)*16u, xs + tid + i*NTHR);
        CP_COMMIT; CP_WAIT0;
    }

    // ---- cell-thread state: cl = tid>>7 (layer), wg = tid&127
    const int cl = tid >> 7;
    const int wg = tid & 127;
    const int b  = wg & 15;
    const int lu = wg >> 4;
    const int u  = cblk * 8 + lu;
    float cc = 0.f;
    float bs0, bs1, bs2, bs3;
    {
        const float* bi = cl ? bih1 : bih0;
        const float* bh = cl ? bhh1 : bhh0;
        bs0 = bi[u]        + bh[u];
        bs1 = bi[H_ + u]   + bh[H_ + u];
        bs2 = bi[2*H_ + u] + bh[2*H_ + u];
        bs3 = bi[3*H_ + u] + bh[3*H_ + u];
    }
    int h_a32;
    {
        int ue = u & ~1;
        int kl = ue & 15;
        int tq_ = (kl >> 1) & 3;
        int rr  = (b >> 3) + ((kl >> 3) << 1);
        int ln_ = ((b & 7) << 2) | tq_;
        h_a32 = ((ue >> 4) * 32 + ln_) * 4 + rr;
    }
    const int myflag = warp * 16 + (lane & 15);
    __syncthreads();

    #pragma unroll 1
    for (int s = 0; s <= T_; ++s) {
        const uint32_t* s_x  = (s & 1) ? s_x1 : s_x0;
        const uint32_t  A_XN = sbase + (uint32_t)(((s + 1) & 1) ? 8192*4 : 0);

        // ---- stage x[s+1] (other parity buffer) ----
        if (s + 1 < T_) {
            const uint4* xs = (const uint4*)(g_xfrag0 + (size_t)(s + 1) * XFRAG_T);
            #pragma unroll
            for (int i = 0; i < 8; i++) cpa16(A_XN + (tid + i*NTHR)*16u, xs + tid + i*NTHR);
        }
        CP_COMMIT;

        // ---- L0 x-GEMM (pre-poll; A and B from smem) ----
        float acc0[4][4];
        #pragma unroll
        for (int nt = 0; nt < 4; nt++)
            #pragma unroll
            for (int j = 0; j < 4; j++) acc0[nt][j] = 0.f;
        if (s < T_) {
            #pragma unroll
            for (int j = 0; j < 8; j++) {
                int kk = warp * 8 + j;
                uint4 a = *(const uint4*)&s_x[(kk * 32 + lane) * 4];
                #pragma unroll
                for (int nt = 0; nt < 4; nt++) {
                    uint2 bb = *(const uint2*)&s_wx0[((kk * 4 + nt) * 32 + lane) * 2];
                    mma16816(acc0[nt], a, bb);
                }
            }
        }

        // ---- targeted poll: my 16 producer CTAs finished interval s-1 ----
        if (s) {
            const unsigned tgt = (unsigned)s;
            for (;;) {
                unsigned v = ld_acq(&g_flags[myflag]);
                if (__all_sync(0xffffffffu, v >= tgt)) break;
                __nanosleep(20);
            }
        }

        // ---- h loads: h0 slice feeds BOTH L0h and L1in; h1 slice feeds L1h ----
        uint4 ah0[8], ah1[8];
        {
            const uint4* h0p = (const uint4*)(g_h0f + (size_t)(s & 1) * HFRAG_SZ);
            const uint4* h1p = (const uint4*)(g_h1f + (size_t)(s & 1) * HFRAG_SZ);
            #pragma unroll
            for (int j = 0; j < 8; j++)
                ah0[j] = ldcg4(h0p + ((warp * 8 + j) * 32 + lane));
            #pragma unroll
            for (int j = 0; j < 8; j++)
                ah1[j] = ldcg4(h1p + ((warp * 8 + j) * 32 + lane));
        }

        // ---- L0 h-GEMM (B from smem) ----
        #pragma unroll
        for (int j = 0; j < 8; j++) {
            int kk = warp * 8 + j;
            #pragma unroll
            for (int nt = 0; nt < 4; nt++) {
                uint2 bb = *(const uint2*)&s_wh0[((kk * 4 + nt) * 32 + lane) * 2];
                mma16816(acc0[nt], ah0[j], bb);
            }
        }
        // store L0 partials early (frees acc0 regs)
        {
            float* rp = s_red + warp * RED_STRIDE;
            #pragma unroll
            for (int nt = 0; nt < 4; nt++) {
                int col = nt * 8 + tq * 2;
                *(float2*)&rp[g * 34 + col]       = make_float2(acc0[nt][0], acc0[nt][1]);
                *(float2*)&rp[(g + 8) * 34 + col] = make_float2(acc0[nt][2], acc0[nt][3]);
            }
        }

        // ---- L1: input-GEMM (A = same ah0) + recurrent GEMM ----
        float acc1[4][4];
        #pragma unroll
        for (int nt = 0; nt < 4; nt++)
            #pragma unroll
            for (int j = 0; j < 4; j++) acc1[nt][j] = 0.f;
        #pragma unroll
        for (int j = 0; j < 8; j++) {
            #pragma unroll
            for (int nt = 0; nt < 4; nt++) mma16816(acc1[nt], ah0[j], bi1r[j][nt]);
        }
        #pragma unroll
        for (int j = 0; j < 8; j++) {
            #pragma unroll
            for (int nt = 0; nt < 4; nt++) mma16816(acc1[nt], ah1[j], bh1r[j][nt]);
        }
        {
            float* rp = s_red + (8 + warp) * RED_STRIDE;
            #pragma unroll
            for (int nt = 0; nt < 4; nt++) {
                int col = nt * 8 + tq * 2;
                *(float2*)&rp[g * 34 + col]       = make_float2(acc1[nt][0], acc1[nt][1]);
                *(float2*)&rp[(g + 8) * 34 + col] = make_float2(acc1[nt][2], acc1[nt][3]);
            }
        }
        __syncthreads();                       // partials visible

        // ---- cells: warps 0-3 -> L0 (step s), warps 4-7 -> L1 (step s-1) ----
        {
            bool active = cl ? (s >= 1) : (s < T_);
            if (active) {
                float gi = bs0, gf = bs1, gg = bs2, go = bs3;
                const float* rb = s_red + (cl * 8) * RED_STRIDE + b * 34;
                #pragma unroll
                for (int w = 0; w < 8; w++) {
                    const float* rp = rb + w * RED_STRIDE;
                    gi += rp[lu];
                    gf += rp[8 + lu];
                    gg += rp[16 + lu];
                    go += rp[24 + lu];
                }
                float fi = sigmoid_ap(gi);
                float ff = sigmoid_ap(gf);
                float fg = tanh_ap(gg);
                float fo = sigmoid_ap(go);
                cc = ff * cc + fi * fg;
                float hv = fo * tanh_ap(cc);

                unsigned us = (unsigned)__half_as_ushort(__float2half_rn(hv));
                unsigned other = __shfl_xor_sync(0xffffffffu, us, 16);
                if (lane < 16) {               // pack (even u | odd u)
                    uint32_t packed = us | (other << 16);
                    uint32_t* dst = cl ? g_h1f : g_h0f;
                    dst[(size_t)((s + 1) & 1) * HFRAG_SZ + h_a32] = packed;
                }
                if (cl)
                    out[((size_t)(s - 1) * B_ + b) * H_ + u] = hv;
                if (nh && s == (cl ? T_ : T_ - 1)) {
                    nh[cl * B_ * H_ + b * H_ + u] = hv;
                    nc[cl * B_ * H_ + b * H_ + u] = cc;
                }
            }
        }
        CP_WAIT0;                              // x[s+1] staged
        __syncthreads();                       // h stores ordered; no run-ahead

        // ---- arrive: one release flag covers h0 and h1 of this CTA ----
        if (tid == 0)
            st_release_u32(&g_flags[cblk], (unsigned)(s + 1));
    }
}

// ---------------------------------------------------------------------------
extern "C" void kernel_launch(void* const* d_in, const int* in_sizes, int n_in,
                              void* d_out, int out_size) {
    const float* x    = (const float*)d_in[0];
    const float* Wih0 = (const float*)d_in[1];
    const float* bih0 = (const float*)d_in[2];
    const float* Whh0 = (const float*)d_in[3];
    const float* bhh0 = (const float*)d_in[4];
    const float* Wih1 = (const float*)d_in[5];
    const float* bih1 = (const float*)d_in[6];
    const float* Whh1 = (const float*)d_in[7];
    const float* bhh1 = (const float*)d_in[8];
    float* out = (float*)d_out;

    float* nh = nullptr;
    float* nc = nullptr;
    const size_t out1_sz = (size_t)T_ * B_ * H_;
    if ((size_t)out_size >= out1_sz + 4 * B_ * H_) {
        nh = out + out1_sz;
        nc = nh + 2 * B_ * H_;
    }

    static bool attr_done = false;
    if (!attr_done) {
        cudaFuncSetAttribute(k_lstm,
                             cudaFuncAttributeMaxDynamicSharedMemorySize, SMEM_BYTES);
        attr_done = true;
    }

    dim3 gw(2048, 2);
    k_conv_w<<<gw, 256>>>(Wih0, Whh0, Wih1, Whh1);
    k_conv_x<<<4096, 256>>>(x);
    k_reset<<<128, 256>>>();
    k_lstm<<<NCTA, NTHR, SMEM_BYTES>>>(bih0, bhh0, bih1, bhh1, out, nh, nc);
}

// round 13
// speedup vs baseline: 1.8508x; 1.8508x over previous
#include <cuda_runtime.h>
#include <cuda_fp16.h>
#include <cstdint>
#include <cstddef>

// 2-layer LSTM, T=1024, B=16, I=H=1024.
// R10 structure: persistent per-layer kernels; 256 thr; register weights;
// parity-buffered cp.async x staging; x-GEMM split around targeted poll;
// h direct from L2; early flag release; no run-ahead.
// R13 delta: transposed reduction layout -> cell loads via LDS.128.
#define T_   1024
#define B_   16
#define H_   1024
#define NCTA 128
#define NTHR 256
#define WFRAG_L (NCTA*128*4*32*2)     // u32 per layer = 4,194,304
#define XFRAG_T 8192                  // u32 per timestep A-frag (32 KB)
#define HFRAG_SZ XFRAG_T
#define RED_STRIDE 576                // 16 rows * 36 floats per warp
// smem: s_x[2][8192] u32 (64 KB) + s_red[8*576] f32 (18432 B)
#define SMEM_BYTES (2*8192*4 + 8*RED_STRIDE*4)   // 83968 B

__device__ __align__(16) uint32_t g_wfrag[2][WFRAG_L];
__device__ __align__(16) uint32_t g_xfrag0[(size_t)T_*XFRAG_T];
__device__ __align__(16) uint32_t g_xfrag1[(size_t)T_*XFRAG_T];
__device__ __align__(16) uint32_t g_hfrag[2*HFRAG_SZ];
__device__ __align__(16) unsigned g_flags[NCTA];

// ---------------------------------------------------------------------------
__global__ void k_reset() {
    int i = blockIdx.x * blockDim.x + threadIdx.x;
    if (i < 2*HFRAG_SZ) g_hfrag[i] = 0u;
    if (i < NCTA) g_flags[i] = 0u;
}

// B-frag layout for [Wih;Whh]: idx = (((c*128+kk)*4+nt)*32+lane)*2+p
// lane=4g+tq ; W row = nt*H + c*8 + g ; k = (kk&63)*16 + 2tq + 8p + {0,1}
// kk<64 -> Wih, kk>=64 -> Whh
__global__ void k_conv_w(const float* __restrict__ Wih0, const float* __restrict__ Whh0,
                         const float* __restrict__ Wih1, const float* __restrict__ Whh1) {
    int layer = blockIdx.y;
    const float* Wih = layer ? Wih1 : Wih0;
    const float* Whh = layer ? Whh1 : Whh0;
    int stride = gridDim.x * blockDim.x;
    for (int idx = blockIdx.x * blockDim.x + threadIdx.x; idx < WFRAG_L; idx += stride) {
        int p    = idx & 1;
        int lane = (idx >> 1) & 31;
        int nt   = (idx >> 6) & 3;
        int kk   = (idx >> 8) & 127;
        int c    = idx >> 15;
        int g = lane >> 2, tq = lane & 3;
        int row = nt * H_ + c * 8 + g;
        int kl  = (kk & 63) * 16 + tq * 2 + p * 8;
        const float2 v = *reinterpret_cast<const float2*>(
            (kk < 64 ? Wih : Whh) + (size_t)row * H_ + kl);
        __half2 hv = __floats2half2_rn(v.x, v.y);
        g_wfrag[layer][idx] = *reinterpret_cast<uint32_t*>(&hv);
    }
}

// A-frag layout for x: per-t idx = (kk*32+lane)*4 + r ; b = g + 8*(r&1) ;
// k = kk*16 + 2tq + 8*(r>>1) + {0,1}
__global__ void k_conv_x(const float* __restrict__ x) {
    size_t total = (size_t)T_ * XFRAG_T;
    size_t stride = (size_t)gridDim.x * blockDim.x;
    for (size_t idx = (size_t)blockIdx.x * blockDim.x + threadIdx.x; idx < total; idx += stride) {
        int it = (int)(idx >> 13);
        int r8 = (int)(idx & (XFRAG_T - 1));
        int kk   = r8 >> 7;
        int lane = (r8 >> 2) & 31;
        int r    = r8 & 3;
        int g = lane >> 2, tq = lane & 3;
        int b  = g + ((r & 1) << 3);
        int kb = kk * 16 + tq * 2 + ((r >> 1) << 3);
        const float2 v = *reinterpret_cast<const float2*>(
            x + ((size_t)it * B_ + b) * H_ + kb);
        __half2 hv = __floats2half2_rn(v.x, v.y);
        g_xfrag0[idx] = *reinterpret_cast<uint32_t*>(&hv);
    }
}

// ---------------------------------------------------------------------------
__device__ __forceinline__ float tanh_ap(float v) {
    float r;
    asm("tanh.approx.f32 %0, %1;" : "=f"(r) : "f"(v));
    return r;
}
__device__ __forceinline__ float sigmoid_ap(float v) {
    return fmaf(tanh_ap(0.5f * v), 0.5f, 0.5f);
}

__device__ __forceinline__ void cpa16(uint32_t dst, const void* src) {
    asm volatile("cp.async.cg.shared.global [%0], [%1], 16;" :: "r"(dst), "l"(src));
}
#define CP_COMMIT asm volatile("cp.async.commit_group;")
#define CP_WAIT0  asm volatile("cp.async.wait_group 0;")

__device__ __forceinline__ uint4 ldcg4(const uint4* p) {
    uint4 v;
    asm volatile("ld.global.cg.v4.u32 {%0,%1,%2,%3}, [%4];"
                 : "=r"(v.x), "=r"(v.y), "=r"(v.z), "=r"(v.w) : "l"(p));
    return v;
}
__device__ __forceinline__ unsigned ld_acq(const unsigned* p) {
    unsigned v;
    asm volatile("ld.acquire.gpu.global.u32 %0, [%1];" : "=r"(v) : "l"(p));
    return v;
}
__device__ __forceinline__ void st_release_u32(unsigned* p, unsigned v) {
    asm volatile("st.release.gpu.global.u32 [%0], %1;" :: "l"(p), "r"(v) : "memory");
}

__device__ __forceinline__ void mma16816(float* acc, const uint4& a, const uint2& b) {
    asm volatile(
        "mma.sync.aligned.m16n8k16.row.col.f32.f16.f16.f32 "
        "{%0,%1,%2,%3}, {%4,%5,%6,%7}, {%8,%9}, {%0,%1,%2,%3};\n"
        : "+f"(acc[0]), "+f"(acc[1]), "+f"(acc[2]), "+f"(acc[3])
        : "r"(a.x), "r"(a.y), "r"(a.z), "r"(a.w), "r"(b.x), "r"(b.y));
}

__global__ void __launch_bounds__(NTHR, 1)
k_lstm_layer(int layer,
             const float* __restrict__ bih, const float* __restrict__ bhh,
             float* __restrict__ out,          // fp32 [T,B,H] (layer1) or null
             float* __restrict__ nh, float* __restrict__ nc) {
    extern __shared__ uint32_t smem[];
    uint32_t* s_x0  = smem;                    // parity 0 x A-frag
    uint32_t* s_x1  = smem + 8192;             // parity 1 x A-frag
    float*    s_red = (float*)(smem + 16384);  // 8*576 floats, layout [w][b][u*4+g]

    uint32_t sbase;
    asm("{ .reg .u64 t; cvta.to.shared.u64 t, %1; cvt.u32.u64 %0, t; }"
        : "=r"(sbase) : "l"(smem));

    const uint32_t* xfrag = layer ? g_xfrag1 : g_xfrag0;

    const int tid = threadIdx.x, warp = tid >> 5, lane = tid & 31;
    const int cblk = blockIdx.x;
    const int g = lane >> 2, tq = lane & 3;

    // ---- weights -> registers: warp covers x-kk [warp*8,+8) and h-kk 64+[warp*8,+8)
    uint2 bxr[8][4], bhr[8][4];
    {
        const uint32_t* wf = g_wfrag[layer] + (size_t)cblk * 32768;
        #pragma unroll
        for (int j = 0; j < 8; j++) {
            #pragma unroll
            for (int nt = 0; nt < 4; nt++) {
                int kkx = warp * 8 + j;
                int kkh = 64 + warp * 8 + j;
                bxr[j][nt] = *(const uint2*)&wf[((kkx * 4 + nt) * 32 + lane) * 2];
                bhr[j][nt] = *(const uint2*)&wf[((kkh * 4 + nt) * 32 + lane) * 2];
            }
        }
    }

    // ---- prologue: x[0] -> s_x0 via cp.async
    {
        const uint4* xs = (const uint4*)xfrag;
        #pragma unroll
        for (int i = 0; i < 8; i++) cpa16(sbase + (tid + i*NTHR)*16u, xs + tid + i*NTHR);
        CP_COMMIT; CP_WAIT0;
    }

    // ---- cell-thread state (tid<128): b = tid&15, unit u = cblk*8 + (tid>>4)
    float cc = 0.f, bs0 = 0.f, bs1 = 0.f, bs2 = 0.f, bs3 = 0.f;
    int b = 0, u = 0, h_a32 = 0;
    if (tid < 128) {
        b = tid & 15;
        int lu = tid >> 4;
        u = cblk * 8 + lu;
        bs0 = bih[u]        + bhh[u];
        bs1 = bih[H_ + u]   + bhh[H_ + u];
        bs2 = bih[2*H_ + u] + bhh[2*H_ + u];
        bs3 = bih[3*H_ + u] + bhh[3*H_ + u];
        int ue = u & ~1;
        int kl = ue & 15;
        int tq_ = (kl >> 1) & 3;
        int rr  = (b >> 3) + ((kl >> 3) << 1);
        int ln_ = ((b & 7) << 2) | tq_;
        h_a32 = ((ue >> 4) * 32 + ln_) * 4 + rr;
    }
    // this warp polls producer CTAs [16*warp, 16*warp+16)
    const int myflag = warp * 16 + (lane & 15);
    __syncthreads();

    #pragma unroll 1
    for (int t = 0; t < T_; ++t) {
        const uint32_t* s_x  = (t & 1) ? s_x1 : s_x0;
        const uint32_t  A_XN = sbase + (uint32_t)(((t + 1) & 1) ? 8192*4 : 0);

        // ---- stage x[t+1] into the other parity buffer ----
        if (t + 1 < T_) {
            const uint4* xs = (const uint4*)(xfrag + (size_t)(t + 1) * XFRAG_T);
            #pragma unroll
            for (int i = 0; i < 8; i++) cpa16(A_XN + (tid + i*NTHR)*16u, xs + tid + i*NTHR);
        }
        CP_COMMIT;

        float acc[4][4];
        #pragma unroll
        for (int nt = 0; nt < 4; nt++)
            #pragma unroll
            for (int j = 0; j < 4; j++) acc[nt][j] = 0.f;

        // ---- x-GEMM part 1 (producer-independent) ----
        #pragma unroll
        for (int j = 0; j < 4; j++) {
            uint4 a = *(const uint4*)&s_x[((warp * 8 + j) * 32 + lane) * 4];
            #pragma unroll
            for (int nt = 0; nt < 4; nt++) mma16816(acc[nt], a, bxr[j][nt]);
        }

        // ---- targeted poll: my 16 producer CTAs done with step t-1 ----
        if (t) {
            const unsigned tgt = (unsigned)t;
            for (;;) {
                unsigned v = ld_acq(&g_flags[myflag]);
                if (__all_sync(0xffffffffu, v >= tgt)) break;
                __nanosleep(20);
            }
        }

        // ---- issue h A-frag LDGs; latency hidden by x-GEMM part 2 ----
        uint4 ah[8];
        {
            const uint4* ha = (const uint4*)(g_hfrag + (size_t)(t & 1) * HFRAG_SZ);
            #pragma unroll
            for (int j = 0; j < 8; j++)
                ah[j] = ldcg4(ha + ((warp * 8 + j) * 32 + lane));
        }

        // ---- x-GEMM part 2 ----
        #pragma unroll
        for (int j = 4; j < 8; j++) {
            uint4 a = *(const uint4*)&s_x[((warp * 8 + j) * 32 + lane) * 4];
            #pragma unroll
            for (int nt = 0; nt < 4; nt++) mma16816(acc[nt], a, bxr[j][nt]);
        }

        // ---- h-GEMM ----
        #pragma unroll
        for (int j = 0; j < 8; j++) {
            #pragma unroll
            for (int nt = 0; nt < 4; nt++) mma16816(acc[nt], ah[j], bhr[j][nt]);
        }

        // ---- partials -> s_red[warp][b][u*4 + gate] (transposed layout) ----
        {
            float* rp = s_red + warp * RED_STRIDE;
            #pragma unroll
            for (int nt = 0; nt < 4; nt++) {
                int c0 = (tq * 2) * 4 + nt;        // unit 2tq,  gate nt
                int c1 = (tq * 2 + 1) * 4 + nt;    // unit 2tq+1, gate nt
                rp[g * 36 + c0]       = acc[nt][0];
                rp[g * 36 + c1]       = acc[nt][1];
                rp[(g + 8) * 36 + c0] = acc[nt][2];
                rp[(g + 8) * 36 + c1] = acc[nt][3];
            }
        }
        __syncthreads();                       // red visible to cell warps

        // ---- cell update (warps 0-3); others idle at the bottom sync ----
        if (tid < 128) {
            int lu = tid >> 4;
            float gi = bs0, gf = bs1, gg = bs2, go = bs3;
            const float* rb = s_red + b * 36 + lu * 4;   // 16B-aligned
            #pragma unroll
            for (int w = 0; w < 8; w++) {
                float4 v = *(const float4*)&rb[w * RED_STRIDE];
                gi += v.x;
                gf += v.y;
                gg += v.z;
                go += v.w;
            }
            float fi = sigmoid_ap(gi);
            float ff = sigmoid_ap(gf);
            float fg = tanh_ap(gg);
            float fo = sigmoid_ap(go);
            cc = ff * cc + fi * fg;
            float hv = fo * tanh_ap(cc);

            unsigned us = (unsigned)__half_as_ushort(__float2half_rn(hv));
            unsigned other = __shfl_xor_sync(0xffffffffu, us, 16);
            uint32_t packed = us | (other << 16);
            if (lane < 16)                     // pack (even u | odd u)
                g_hfrag[(size_t)((t + 1) & 1) * HFRAG_SZ + h_a32] = packed;

            // early publish: h stores HB-ordered by named bar, then release
            asm volatile("bar.sync 1, 128;" ::: "memory");
            if (tid == 0)
                st_release_u32(&g_flags[cblk], (unsigned)(t + 1));

            // off-critical-path stores
            if (layer == 0 && lane < 16)
                g_xfrag1[(size_t)t * XFRAG_T + h_a32] = packed;
            if (layer == 1)
                out[((size_t)t * B_ + b) * H_ + u] = hv;
            if (t == T_ - 1 && nh) {
                nh[b * H_ + u] = hv;
                nc[b * H_ + u] = cc;
            }
        }
        CP_WAIT0;                              // own x[t+1] group done
        __syncthreads();                       // no run-ahead past this point
    }
}

// ---------------------------------------------------------------------------
extern "C" void kernel_launch(void* const* d_in, const int* in_sizes, int n_in,
                              void* d_out, int out_size) {
    const float* x    = (const float*)d_in[0];
    const float* Wih0 = (const float*)d_in[1];
    const float* bih0 = (const float*)d_in[2];
    const float* Whh0 = (const float*)d_in[3];
    const float* bhh0 = (const float*)d_in[4];
    const float* Wih1 = (const float*)d_in[5];
    const float* bih1 = (const float*)d_in[6];
    const float* Whh1 = (const float*)d_in[7];
    const float* bhh1 = (const float*)d_in[8];
    float* out = (float*)d_out;

    float* nh = nullptr;
    float* nc = nullptr;
    const size_t out1_sz = (size_t)T_ * B_ * H_;
    if ((size_t)out_size >= out1_sz + 4 * B_ * H_) {
        nh = out + out1_sz;
        nc = nh + 2 * B_ * H_;
    }

    static bool attr_done = false;
    if (!attr_done) {
        cudaFuncSetAttribute(k_lstm_layer,
                             cudaFuncAttributeMaxDynamicSharedMemorySize, SMEM_BYTES);
        attr_done = true;
    }

    dim3 gw(2048, 2);
    k_conv_w<<<gw, 256>>>(Wih0, Whh0, Wih1, Whh1);
    k_conv_x<<<4096, 256>>>(x);

    k_reset<<<128, 256>>>();
    k_lstm_layer<<<NCTA, NTHR, SMEM_BYTES>>>(0, bih0, bhh0, nullptr, nh, nc);
    k_reset<<<128, 256>>>();
    k_lstm_layer<<<NCTA, NTHR, SMEM_BYTES>>>(1, bih1, bhh1, out,
                                             nh ? nh + B_ * H_ : nullptr,
                                             nc ? nc + B_ * H_ : nullptr);
}